// round 12
// baseline (speedup 1.0000x reference)
#include <cuda_runtime.h>
#include <cuda_bf16.h>
#include <math_constants.h>

#define B_  8
#define SQ_ 128
#define SK_ 1024
#define U_  256

// Scratch: projections in MIXED layout (u%4 in {0,1}: raw, {2,3}: tanh'd)
__device__ float g_q[B_ * SQ_ * U_];   // 1 MB
__device__ float g_k[B_ * SK_ * U_];   // 8 MB

__device__ __forceinline__ float tanha(float x) {
    float y;
    asm("tanh.approx.f32 %0, %1;" : "=f"(y) : "f"(x));
    return y;
}

// ---- packed f32x2 ops (Blackwell paired-FP32; ptxas never auto-emits) ----
typedef unsigned long long ull;
#define ONE2_  0x3F8000003F800000ULL
#define TWO2_  0x4000000040000000ULL
#define SIGN2_ 0x8000000080000000ULL
#define MAGIC2_ 0x7EF311C37EF311C3ULL

__device__ __forceinline__ ull fma2(ull a, ull b, ull c) {
    ull d; asm("fma.rn.f32x2 %0, %1, %2, %3;" : "=l"(d) : "l"(a), "l"(b), "l"(c));
    return d;
}
__device__ __forceinline__ ull add2(ull a, ull b) {
    ull d; asm("add.rn.f32x2 %0, %1, %2;" : "=l"(d) : "l"(a), "l"(b));
    return d;
}
__device__ __forceinline__ ull mul2(ull a, ull b) {
    ull d; asm("mul.rn.f32x2 %0, %1, %2;" : "=l"(d) : "l"(a), "l"(b));
    return d;
}
__device__ __forceinline__ ull pack2(float lo, float hi) {
    ull d; asm("mov.b64 %0, {%1, %2};" : "=l"(d) : "f"(lo), "f"(hi));
    return d;
}
__device__ __forceinline__ void unpack2(ull v, float& lo, float& hi) {
    asm("mov.b64 {%0, %1}, %2;" : "=f"(lo), "=f"(hi) : "l"(v));
}

__device__ __forceinline__ unsigned smem_u32(const void* p) {
    return (unsigned)__cvta_generic_to_shared(p);
}

// ---------------------------------------------------------------------------
// bf16 3-term split GEMM helpers
// ---------------------------------------------------------------------------
__device__ __forceinline__ void split_store8(float4 v,
                                             __nv_bfloat16* ph, __nv_bfloat16* pl) {
    __nv_bfloat162 h01 = __floats2bfloat162_rn(v.x, v.y);
    __nv_bfloat162 h23 = __floats2bfloat162_rn(v.z, v.w);
    __nv_bfloat162 l01 = __floats2bfloat162_rn(v.x - __bfloat162float(h01.x),
                                               v.y - __bfloat162float(h01.y));
    __nv_bfloat162 l23 = __floats2bfloat162_rn(v.z - __bfloat162float(h23.x),
                                               v.w - __bfloat162float(h23.y));
    *reinterpret_cast<__nv_bfloat162*>(ph)     = h01;
    *reinterpret_cast<__nv_bfloat162*>(ph + 2) = h23;
    *reinterpret_cast<__nv_bfloat162*>(pl)     = l01;
    *reinterpret_cast<__nv_bfloat162*>(pl + 2) = l23;
}

__device__ __forceinline__ void ldsm_x4(unsigned r[4], unsigned addr) {
    asm volatile("ldmatrix.sync.aligned.m8n8.x4.shared.b16 {%0,%1,%2,%3}, [%4];"
        : "=r"(r[0]), "=r"(r[1]), "=r"(r[2]), "=r"(r[3]) : "r"(addr));
}

__device__ __forceinline__ void ldsm_x4_t(unsigned r[4], unsigned addr) {
    asm volatile("ldmatrix.sync.aligned.m8n8.x4.trans.shared.b16 {%0,%1,%2,%3}, [%4];"
        : "=r"(r[0]), "=r"(r[1]), "=r"(r[2]), "=r"(r[3]) : "r"(addr));
}

__device__ __forceinline__ void mma_bf16(float* d, const unsigned a[4],
                                         unsigned b0, unsigned b1) {
    asm volatile("mma.sync.aligned.m16n8k16.row.col.f32.bf16.bf16.f32 "
        "{%0,%1,%2,%3}, {%4,%5,%6,%7}, {%8,%9}, {%0,%1,%2,%3};"
        : "+f"(d[0]), "+f"(d[1]), "+f"(d[2]), "+f"(d[3])
        : "r"(a[0]), "r"(a[1]), "r"(a[2]), "r"(a[3]), "r"(b0), "r"(b1));
}

// ---------------------------------------------------------------------------
// Tensor-core SGEMM, bf16 3-term split. MIXEPI=1: tanh cols %4 in {2,3}.
// ---------------------------------------------------------------------------
template <int IM, int MIXEPI>
__global__ void gemm_tc(const float* __restrict__ A, const float* __restrict__ Bm,
                        float* __restrict__ C, int M, int N, int K,
                        long long sA, long long sB, long long sC) {
    constexpr int TM = 32 * IM;
    A  += (long long)blockIdx.z * sA;
    Bm += (long long)blockIdx.z * sB;
    C  += (long long)blockIdx.z * sC;

    __shared__ alignas(16) __nv_bfloat16 Ah[TM][40], Al[TM][40];
    __shared__ alignas(16) __nv_bfloat16 Bh[32][72], Bl[32][72];

    const int tid  = threadIdx.x;
    const int lane = tid & 31;
    const int warp = tid >> 5;
    const int wm   = warp >> 2;
    const int wn   = warp & 3;
    const int gid  = lane >> 2;
    const int tig  = lane & 3;
    const int m_base = wm * (16 * IM);
    const int n_base = wn * 16;
    const int m0 = blockIdx.y * TM;
    const int n0 = blockIdx.x * 64;

    const int l8   = lane & 7;
    const int t8   = lane >> 3;
    const int rrow = l8 + ((t8 & 1) << 3);
    const int rcol = (t8 >> 1) << 3;

    const unsigned baseAh = smem_u32(&Ah[0][0]);
    const unsigned baseAl = smem_u32(&Al[0][0]);
    const unsigned baseBh = smem_u32(&Bh[0][0]);
    const unsigned baseBl = smem_u32(&Bl[0][0]);

    float acc[IM][2][4];
#pragma unroll
    for (int im = 0; im < IM; im++)
#pragma unroll
        for (int in = 0; in < 2; in++)
#pragma unroll
            for (int c = 0; c < 4; c++) acc[im][in][c] = 0.0f;

    for (int k0 = 0; k0 < K; k0 += 32) {
#pragma unroll
        for (int it = 0; it < IM; it++) {
            int idx = tid + it * 256;
            int r = idx >> 3;
            int c = (idx & 7) << 2;
            float4 v = *(const float4*)&A[(long long)(m0 + r) * K + k0 + c];
            split_store8(v, &Ah[r][c], &Al[r][c]);
        }
#pragma unroll
        for (int it = 0; it < 2; it++) {
            int idx = tid + it * 256;
            int r = idx >> 4;
            int c = (idx & 15) << 2;
            float4 v = *(const float4*)&Bm[(long long)(k0 + r) * N + n0 + c];
            split_store8(v, &Bh[r][c], &Bl[r][c]);
        }
        __syncthreads();

#pragma unroll
        for (int kk = 0; kk < 2; kk++) {
            const int kb = kk << 4;
            unsigned ah[IM][4], al[IM][4], bh[4], bl[4];
#pragma unroll
            for (int im = 0; im < IM; im++) {
                unsigned ra = ((unsigned)((m_base + 16 * im + rrow) * 40 + kb + rcol)) << 1;
                ldsm_x4(ah[im], baseAh + ra);
                ldsm_x4(al[im], baseAl + ra);
            }
            unsigned rb = ((unsigned)((kb + rrow) * 72 + n_base + rcol)) << 1;
            ldsm_x4_t(bh, baseBh + rb);
            ldsm_x4_t(bl, baseBl + rb);

#pragma unroll
            for (int im = 0; im < IM; im++) {
                mma_bf16(acc[im][0], ah[im], bh[0], bh[1]);
                mma_bf16(acc[im][0], ah[im], bl[0], bl[1]);
                mma_bf16(acc[im][0], al[im], bh[0], bh[1]);
                mma_bf16(acc[im][1], ah[im], bh[2], bh[3]);
                mma_bf16(acc[im][1], ah[im], bl[2], bl[3]);
                mma_bf16(acc[im][1], al[im], bh[2], bh[3]);
            }
        }
        __syncthreads();
    }

    const bool dotanh = MIXEPI && (tig & 1);
#pragma unroll
    for (int im = 0; im < IM; im++) {
#pragma unroll
        for (int in = 0; in < 2; in++) {
            int row = m0 + m_base + 16 * im + gid;
            int col = n0 + n_base + 8 * in + 2 * tig;
            float* d = acc[im][in];
            if (dotanh) {
#pragma unroll
                for (int c = 0; c < 4; c++) d[c] = tanha(d[c]);
            }
            *(float2*)&C[(long long)row * N + col]       = make_float2(d[0], d[1]);
            *(float2*)&C[(long long)(row + 8) * N + col] = make_float2(d[2], d[3]);
        }
    }
}

// ---------------------------------------------------------------------------
// Scores v7: MUFU tanh on x,y components; packed f32x2 identity path on the
// pre-tanh'd z,w components. Per identity PAIR: 7 FFMA2 + u64 seed/neg.
// Split smem layouts avoid per-iteration repacking.
// ---------------------------------------------------------------------------
#define TQ 16

__global__ void scores_kernel(const float* __restrict__ wv, float* __restrict__ attn) {
    const int b  = blockIdx.z;
    const int ib = blockIdx.y;
    const int tid = threadIdx.x;
    const int j  = blockIdx.x * 256 + tid;

    __shared__ float qxy[TQ][U_ / 2];        // raw x,y comps        (8 KB)
    __shared__ alignas(16) ull qzw[TQ][U_ / 4];  // tanh'd z,w pairs (8 KB)
    __shared__ alignas(16) ull qw [TQ][U_ / 4];  // (tq*w) pairs     (8 KB)
    __shared__ float wvs[U_];                // 1 KB

    // Phase 1: load q tile into split layouts + wv
    const float* qbase = g_q + ((long long)(b * SQ_ + ib * TQ)) * U_;
#pragma unroll
    for (int l = 0; l < 4; l++) {
        int idx = tid + l * 256;
        int row = idx >> 6;
        int c   = idx & 63;            // float4 group index
        float4 v = *(const float4*)&qbase[(long long)row * U_ + (c << 2)];
        qxy[row][2 * c]     = v.x;
        qxy[row][2 * c + 1] = v.y;
        qzw[row][c] = pack2(v.z, v.w);
    }
    if (tid < 64) *(float4*)&wvs[tid << 2] = *(const float4*)&wv[tid << 2];
    __syncthreads();

    // Phase 2: qw = tq * w (packed), needs wvs
#pragma unroll
    for (int l = 0; l < 4; l++) {
        int idx = tid + l * 256;
        int row = idx >> 6;
        int c   = idx & 63;
        float zz, ww;
        unpack2(qzw[row][c], zz, ww);
        qw[row][c] = pack2(zz * wvs[4 * c + 2], ww * wvs[4 * c + 3]);
    }
    __syncthreads();

    const float* kp = g_k + ((long long)(b * SK_) + j) * U_;

    float acc1[TQ];          // MUFU-path accumulators
    ull   acc2[TQ];          // identity-path packed accumulators
#pragma unroll
    for (int i = 0; i < TQ; i++) { acc1[i] = 0.0f; acc2[i] = 0ULL; }

    float4 ka = *(const float4*)&kp[0];
    float4 kb = *(const float4*)&kp[4];

    for (int uc = 0; uc < U_; uc += 8) {
        int un = (uc + 8 < U_) ? uc + 8 : uc;   // clamped tail prefetch
        float4 kna = *(const float4*)&kp[un];
        float4 knb = *(const float4*)&kp[un + 4];
        float4 w0 = *(const float4*)&wvs[uc];
        float4 w1 = *(const float4*)&wvs[uc + 4];

        // per-chunk packed k values (amortized over TQ i's)
        ull kzw_a = pack2(ka.z, ka.w);
        ull kzw_b = pack2(kb.z, kb.w);
        ull tkw_a = mul2(kzw_a, pack2(w0.z, w0.w));   // tk*w
        ull tkw_b = mul2(kzw_b, pack2(w1.z, w1.w));

        const int g = uc >> 2;     // float4 group
#pragma unroll
        for (int i = 0; i < TQ; i++) {
            float4 qx = *(const float4*)&qxy[i][uc >> 1];      // x0,y0,x1,y1
            ulonglong2 qz = *(const ulonglong2*)&qzw[i][g];    // (z0w0),(z1w1)
            ulonglong2 qv = *(const ulonglong2*)&qw[i][g];

            // MUFU path (raw x, y)
            float a = acc1[i];
            a = fmaf(tanha(qx.x + ka.x), w0.x, a);
            a = fmaf(tanha(qx.y + ka.y), w0.y, a);
            a = fmaf(tanha(qx.z + kb.x), w1.x, a);
            a = fmaf(tanha(qx.w + kb.y), w1.y, a);
            acc1[i] = a;

            // identity path, packed pair A
            ull c2 = acc2[i];
            {
                ull den  = fma2(qz.x, kzw_a, ONE2_);
                ull y    = MAGIC2_ - den;              // packed seed (no borrow)
                ull nden = den ^ SIGN2_;
                y = mul2(y, fma2(nden, y, TWO2_));
                y = mul2(y, fma2(nden, y, TWO2_));
                ull nmw = add2(qv.x, tkw_a);           // (tq+tk)*w
                c2 = fma2(nmw, y, c2);
            }
            // packed pair B
            {
                ull den  = fma2(qz.y, kzw_b, ONE2_);
                ull y    = MAGIC2_ - den;
                ull nden = den ^ SIGN2_;
                y = mul2(y, fma2(nden, y, TWO2_));
                y = mul2(y, fma2(nden, y, TWO2_));
                ull nmw = add2(qv.y, tkw_b);
                c2 = fma2(nmw, y, c2);
            }
            acc2[i] = c2;
        }
        ka = kna;
        kb = knb;
    }

    long long base = ((long long)(b * SQ_ + ib * TQ)) * SK_ + j;
#pragma unroll
    for (int i = 0; i < TQ; i++) {
        float lo, hi;
        unpack2(acc2[i], lo, hi);
        attn[base + (long long)i * SK_] = acc1[i] + lo + hi;
    }
}

// ---------------------------------------------------------------------------
// Row softmax over SK=1024, in place. One CTA (256 threads) per (b,i) row.
// ---------------------------------------------------------------------------
__global__ void softmax_kernel(float* __restrict__ attn) {
    float* p = attn + (long long)blockIdx.x * SK_;
    const int tid = threadIdx.x;
    __shared__ float red[8];

    float4 x = *(const float4*)&p[tid << 2];
    float m = fmaxf(fmaxf(x.x, x.y), fmaxf(x.z, x.w));
#pragma unroll
    for (int o = 16; o; o >>= 1) m = fmaxf(m, __shfl_xor_sync(0xffffffffu, m, o));
    if ((tid & 31) == 0) red[tid >> 5] = m;
    __syncthreads();
    float M = red[0];
#pragma unroll
    for (int w = 1; w < 8; w++) M = fmaxf(M, red[w]);

    float4 e;
    e.x = __expf(x.x - M);
    e.y = __expf(x.y - M);
    e.z = __expf(x.z - M);
    e.w = __expf(x.w - M);
    float s = (e.x + e.y) + (e.z + e.w);
#pragma unroll
    for (int o = 16; o; o >>= 1) s += __shfl_xor_sync(0xffffffffu, s, o);
    __syncthreads();
    if ((tid & 31) == 0) red[tid >> 5] = s;
    __syncthreads();
    float S = 0.f;
#pragma unroll
    for (int w = 0; w < 8; w++) S += red[w];
    float inv = 1.0f / S;
    e.x *= inv; e.y *= inv; e.z *= inv; e.w *= inv;
    *(float4*)&p[tid << 2] = e;
}

// ---------------------------------------------------------------------------
extern "C" void kernel_launch(void* const* d_in, const int* in_sizes, int n_in,
                              void* d_out, int out_size) {
    const float* query = (const float*)d_in[0];
    const float* key   = (const float*)d_in[1];
    const float* value = (const float*)d_in[2];
    const float* Wq    = (const float*)d_in[3];
    const float* Wk    = (const float*)d_in[4];
    const float* wv    = (const float*)d_in[5];

    float* out  = (float*)d_out;
    float* ctx  = out;                            // [B, SQ, U]
    float* attn = out + (long long)B_ * SQ_ * U_; // [B, SQ, SK]

    void* pq = nullptr; void* pk = nullptr;
    cudaGetSymbolAddress(&pq, g_q);
    cudaGetSymbolAddress(&pk, g_k);
    float* dq = (float*)pq;
    float* dk = (float*)pk;

    // 1) Projections on tensor cores, MIXED epilogue (raw / tanh'd by u%4)
    gemm_tc<2, 1><<<dim3(U_ / 64, (B_ * SQ_) / 64, 1), 256>>>(
        query, Wq, dq, B_ * SQ_, U_, U_, 0, 0, 0);
    gemm_tc<2, 1><<<dim3(U_ / 64, (B_ * SK_) / 64, 1), 256>>>(
        key, Wk, dk, B_ * SK_, U_, U_, 0, 0, 0);

    // 2) Raw scores (MUFU + packed-f32x2 identity) into attn region
    scores_kernel<<<dim3(SK_ / 256, SQ_ / TQ, B_), 256>>>(wv, attn);

    // 3) Softmax in place
    softmax_kernel<<<B_ * SQ_, 256>>>(attn);

    // 4) context = attn @ value (batched, plain epilogue)
    gemm_tc<1, 0><<<dim3(U_ / 64, SQ_ / 32, B_), 256>>>(
        attn, value, ctx, SQ_, U_, SK_,
        (long long)SQ_ * SK_, (long long)SK_ * U_, (long long)SQ_ * U_);
}

// round 13
// speedup vs baseline: 1.0769x; 1.0769x over previous
#include <cuda_runtime.h>
#include <cuda_bf16.h>
#include <math_constants.h>

#define B_  8
#define SQ_ 128
#define SK_ 1024
#define U_  256

// Scratch: projections in MIXED layout (u%4 in {0,1,2}: raw, {3}: tanh'd)
__device__ float g_q[B_ * SQ_ * U_];   // 1 MB
__device__ float g_k[B_ * SK_ * U_];   // 8 MB

__device__ __forceinline__ float tanha(float x) {
    float y;
    asm("tanh.approx.f32 %0, %1;" : "=f"(y) : "f"(x));
    return y;
}

// Division-free reciprocal: magic-constant seed (ALU) + 2 Newton (FMA pipe).
__device__ __forceinline__ float rcp_fma(float den) {
    float y = __uint_as_float(0x7EF311C3u - __float_as_uint(den));
    y = y * (2.0f - den * y);
    y = y * (2.0f - den * y);
    return y;
}

__device__ __forceinline__ unsigned smem_u32(const void* p) {
    return (unsigned)__cvta_generic_to_shared(p);
}

// ---------------------------------------------------------------------------
// bf16 3-term split GEMM helpers
// ---------------------------------------------------------------------------
__device__ __forceinline__ void split_store8(float4 v,
                                             __nv_bfloat16* ph, __nv_bfloat16* pl) {
    __nv_bfloat162 h01 = __floats2bfloat162_rn(v.x, v.y);
    __nv_bfloat162 h23 = __floats2bfloat162_rn(v.z, v.w);
    __nv_bfloat162 l01 = __floats2bfloat162_rn(v.x - __bfloat162float(h01.x),
                                               v.y - __bfloat162float(h01.y));
    __nv_bfloat162 l23 = __floats2bfloat162_rn(v.z - __bfloat162float(h23.x),
                                               v.w - __bfloat162float(h23.y));
    *reinterpret_cast<__nv_bfloat162*>(ph)     = h01;
    *reinterpret_cast<__nv_bfloat162*>(ph + 2) = h23;
    *reinterpret_cast<__nv_bfloat162*>(pl)     = l01;
    *reinterpret_cast<__nv_bfloat162*>(pl + 2) = l23;
}

__device__ __forceinline__ void ldsm_x4(unsigned r[4], unsigned addr) {
    asm volatile("ldmatrix.sync.aligned.m8n8.x4.shared.b16 {%0,%1,%2,%3}, [%4];"
        : "=r"(r[0]), "=r"(r[1]), "=r"(r[2]), "=r"(r[3]) : "r"(addr));
}

__device__ __forceinline__ void ldsm_x4_t(unsigned r[4], unsigned addr) {
    asm volatile("ldmatrix.sync.aligned.m8n8.x4.trans.shared.b16 {%0,%1,%2,%3}, [%4];"
        : "=r"(r[0]), "=r"(r[1]), "=r"(r[2]), "=r"(r[3]) : "r"(addr));
}

__device__ __forceinline__ void mma_bf16(float* d, const unsigned a[4],
                                         unsigned b0, unsigned b1) {
    asm volatile("mma.sync.aligned.m16n8k16.row.col.f32.bf16.bf16.f32 "
        "{%0,%1,%2,%3}, {%4,%5,%6,%7}, {%8,%9}, {%0,%1,%2,%3};"
        : "+f"(d[0]), "+f"(d[1]), "+f"(d[2]), "+f"(d[3])
        : "r"(a[0]), "r"(a[1]), "r"(a[2]), "r"(a[3]), "r"(b0), "r"(b1));
}

// ---------------------------------------------------------------------------
// Tensor-core SGEMM, bf16 3-term split. MIXEPI=1: tanh cols with col%4 == 3
// (i.e. d[1], d[3] on threads with tig odd).
// ---------------------------------------------------------------------------
template <int IM, int MIXEPI>
__global__ void gemm_tc(const float* __restrict__ A, const float* __restrict__ Bm,
                        float* __restrict__ C, int M, int N, int K,
                        long long sA, long long sB, long long sC) {
    constexpr int TM = 32 * IM;
    A  += (long long)blockIdx.z * sA;
    Bm += (long long)blockIdx.z * sB;
    C  += (long long)blockIdx.z * sC;

    __shared__ alignas(16) __nv_bfloat16 Ah[TM][40], Al[TM][40];
    __shared__ alignas(16) __nv_bfloat16 Bh[32][72], Bl[32][72];

    const int tid  = threadIdx.x;
    const int lane = tid & 31;
    const int warp = tid >> 5;
    const int wm   = warp >> 2;
    const int wn   = warp & 3;
    const int gid  = lane >> 2;
    const int tig  = lane & 3;
    const int m_base = wm * (16 * IM);
    const int n_base = wn * 16;
    const int m0 = blockIdx.y * TM;
    const int n0 = blockIdx.x * 64;

    const int l8   = lane & 7;
    const int t8   = lane >> 3;
    const int rrow = l8 + ((t8 & 1) << 3);
    const int rcol = (t8 >> 1) << 3;

    const unsigned baseAh = smem_u32(&Ah[0][0]);
    const unsigned baseAl = smem_u32(&Al[0][0]);
    const unsigned baseBh = smem_u32(&Bh[0][0]);
    const unsigned baseBl = smem_u32(&Bl[0][0]);

    float acc[IM][2][4];
#pragma unroll
    for (int im = 0; im < IM; im++)
#pragma unroll
        for (int in = 0; in < 2; in++)
#pragma unroll
            for (int c = 0; c < 4; c++) acc[im][in][c] = 0.0f;

    for (int k0 = 0; k0 < K; k0 += 32) {
#pragma unroll
        for (int it = 0; it < IM; it++) {
            int idx = tid + it * 256;
            int r = idx >> 3;
            int c = (idx & 7) << 2;
            float4 v = *(const float4*)&A[(long long)(m0 + r) * K + k0 + c];
            split_store8(v, &Ah[r][c], &Al[r][c]);
        }
#pragma unroll
        for (int it = 0; it < 2; it++) {
            int idx = tid + it * 256;
            int r = idx >> 4;
            int c = (idx & 15) << 2;
            float4 v = *(const float4*)&Bm[(long long)(k0 + r) * N + n0 + c];
            split_store8(v, &Bh[r][c], &Bl[r][c]);
        }
        __syncthreads();

#pragma unroll
        for (int kk = 0; kk < 2; kk++) {
            const int kb = kk << 4;
            unsigned ah[IM][4], al[IM][4], bh[4], bl[4];
#pragma unroll
            for (int im = 0; im < IM; im++) {
                unsigned ra = ((unsigned)((m_base + 16 * im + rrow) * 40 + kb + rcol)) << 1;
                ldsm_x4(ah[im], baseAh + ra);
                ldsm_x4(al[im], baseAl + ra);
            }
            unsigned rb = ((unsigned)((kb + rrow) * 72 + n_base + rcol)) << 1;
            ldsm_x4_t(bh, baseBh + rb);
            ldsm_x4_t(bl, baseBl + rb);

#pragma unroll
            for (int im = 0; im < IM; im++) {
                mma_bf16(acc[im][0], ah[im], bh[0], bh[1]);
                mma_bf16(acc[im][0], ah[im], bl[0], bl[1]);
                mma_bf16(acc[im][0], al[im], bh[0], bh[1]);
                mma_bf16(acc[im][1], ah[im], bh[2], bh[3]);
                mma_bf16(acc[im][1], ah[im], bl[2], bl[3]);
                mma_bf16(acc[im][1], al[im], bh[2], bh[3]);
            }
        }
        __syncthreads();
    }

    // MIXEPI: threads with tig odd hold cols {2,3} mod 4 in (d[0],d[1]);
    // tanh only the odd element of each pair -> exactly cols == 3 (mod 4).
    const bool dotanh = MIXEPI && (tig & 1);
#pragma unroll
    for (int im = 0; im < IM; im++) {
#pragma unroll
        for (int in = 0; in < 2; in++) {
            int row = m0 + m_base + 16 * im + gid;
            int col = n0 + n_base + 8 * in + 2 * tig;
            float* d = acc[im][in];
            if (dotanh) {
                d[1] = tanha(d[1]);
                d[3] = tanha(d[3]);
            }
            *(float2*)&C[(long long)row * N + col]       = make_float2(d[0], d[1]);
            *(float2*)&C[(long long)(row + 8) * N + col] = make_float2(d[2], d[3]);
        }
    }
}

// ---------------------------------------------------------------------------
// Scores v8 (3:1 pipe split): components x,y,z of each float4 are RAW ->
// MUFU tanh(q+k). Component w is PRE-TANH'D -> exact addition identity with
// division-free Newton rcp on the FMA pipe.
// Balance: MUFU 0.75*226k = 170k cyc/SM; FMA ~148k (with RF-conflict x1.5).
// ---------------------------------------------------------------------------
#define TQ 16

__global__ void scores_kernel(const float* __restrict__ wv, float* __restrict__ attn) {
    const int b  = blockIdx.z;
    const int ib = blockIdx.y;
    const int tid = threadIdx.x;
    const int j  = blockIdx.x * 256 + tid;

    __shared__ float qs[TQ][U_];   // 16 KB (mixed layout)
    __shared__ float wvs[U_];

    const float* qbase = g_q + ((long long)(b * SQ_ + ib * TQ)) * U_;
#pragma unroll
    for (int l = 0; l < 4; l++) {
        int idx = tid + l * 256;
        int row = idx >> 6;
        int col = (idx & 63) << 2;
        *(float4*)&qs[row][col] = *(const float4*)&qbase[(long long)row * U_ + col];
    }
    if (tid < 64) *(float4*)&wvs[tid << 2] = *(const float4*)&wv[tid << 2];
    __syncthreads();

    const float* kp = g_k + ((long long)(b * SK_) + j) * U_;

    float acc[TQ];
#pragma unroll
    for (int i = 0; i < TQ; i++) acc[i] = 0.0f;

    float4 ka = *(const float4*)&kp[0];
    float4 kb = *(const float4*)&kp[4];

    for (int uc = 0; uc < U_; uc += 8) {
        int un = (uc + 8 < U_) ? uc + 8 : uc;   // clamped tail prefetch
        float4 kna = *(const float4*)&kp[un];
        float4 knb = *(const float4*)&kp[un + 4];
        float4 w0 = *(const float4*)&wvs[uc];
        float4 w1 = *(const float4*)&wvs[uc + 4];
#pragma unroll
        for (int i = 0; i < TQ; i++) {
            float4 q0 = *(const float4*)&qs[i][uc];        // broadcast LDS
            float4 q1 = *(const float4*)&qs[i][uc + 4];
            float a = acc[i];
            // MUFU path (raw components x, y, z)
            a = fmaf(tanha(q0.x + ka.x), w0.x, a);
            a = fmaf(tanha(q0.y + ka.y), w0.y, a);
            a = fmaf(tanha(q0.z + ka.z), w0.z, a);
            a = fmaf(tanha(q1.x + kb.x), w1.x, a);
            a = fmaf(tanha(q1.y + kb.y), w1.y, a);
            a = fmaf(tanha(q1.z + kb.z), w1.z, a);
            // FMA path (pre-tanh'd component w): exact addition identity
            {
                float nm = q0.w + ka.w;
                float r  = rcp_fma(fmaf(q0.w, ka.w, 1.0f));
                a = fmaf(nm * r, w0.w, a);
            }
            {
                float nm = q1.w + kb.w;
                float r  = rcp_fma(fmaf(q1.w, kb.w, 1.0f));
                a = fmaf(nm * r, w1.w, a);
            }
            acc[i] = a;
        }
        ka = kna;
        kb = knb;
    }

    long long base = ((long long)(b * SQ_ + ib * TQ)) * SK_ + j;
#pragma unroll
    for (int i = 0; i < TQ; i++) attn[base + (long long)i * SK_] = acc[i];
}

// ---------------------------------------------------------------------------
// Row softmax over SK=1024, in place. One CTA (256 threads) per (b,i) row.
// ---------------------------------------------------------------------------
__global__ void softmax_kernel(float* __restrict__ attn) {
    float* p = attn + (long long)blockIdx.x * SK_;
    const int tid = threadIdx.x;
    __shared__ float red[8];

    float4 x = *(const float4*)&p[tid << 2];
    float m = fmaxf(fmaxf(x.x, x.y), fmaxf(x.z, x.w));
#pragma unroll
    for (int o = 16; o; o >>= 1) m = fmaxf(m, __shfl_xor_sync(0xffffffffu, m, o));
    if ((tid & 31) == 0) red[tid >> 5] = m;
    __syncthreads();
    float M = red[0];
#pragma unroll
    for (int w = 1; w < 8; w++) M = fmaxf(M, red[w]);

    float4 e;
    e.x = __expf(x.x - M);
    e.y = __expf(x.y - M);
    e.z = __expf(x.z - M);
    e.w = __expf(x.w - M);
    float s = (e.x + e.y) + (e.z + e.w);
#pragma unroll
    for (int o = 16; o; o >>= 1) s += __shfl_xor_sync(0xffffffffu, s, o);
    __syncthreads();
    if ((tid & 31) == 0) red[tid >> 5] = s;
    __syncthreads();
    float S = 0.f;
#pragma unroll
    for (int w = 0; w < 8; w++) S += red[w];
    float inv = 1.0f / S;
    e.x *= inv; e.y *= inv; e.z *= inv; e.w *= inv;
    *(float4*)&p[tid << 2] = e;
}

// ---------------------------------------------------------------------------
extern "C" void kernel_launch(void* const* d_in, const int* in_sizes, int n_in,
                              void* d_out, int out_size) {
    const float* query = (const float*)d_in[0];
    const float* key   = (const float*)d_in[1];
    const float* value = (const float*)d_in[2];
    const float* Wq    = (const float*)d_in[3];
    const float* Wk    = (const float*)d_in[4];
    const float* wv    = (const float*)d_in[5];

    float* out  = (float*)d_out;
    float* ctx  = out;                            // [B, SQ, U]
    float* attn = out + (long long)B_ * SQ_ * U_; // [B, SQ, SK]

    void* pq = nullptr; void* pk = nullptr;
    cudaGetSymbolAddress(&pq, g_q);
    cudaGetSymbolAddress(&pk, g_k);
    float* dq = (float*)pq;
    float* dk = (float*)pk;

    // 1) Projections on tensor cores, MIXED epilogue (tanh on u%4==3)
    gemm_tc<2, 1><<<dim3(U_ / 64, (B_ * SQ_) / 64, 1), 256>>>(
        query, Wq, dq, B_ * SQ_, U_, U_, 0, 0, 0);
    gemm_tc<2, 1><<<dim3(U_ / 64, (B_ * SK_) / 64, 1), 256>>>(
        key, Wk, dk, B_ * SK_, U_, U_, 0, 0, 0);

    // 2) Raw scores (3:1 MUFU/identity split) into attn region
    scores_kernel<<<dim3(SK_ / 256, SQ_ / TQ, B_), 256>>>(wv, attn);

    // 3) Softmax in place
    softmax_kernel<<<B_ * SQ_, 256>>>(attn);

    // 4) context = attn @ value (batched, plain epilogue)
    gemm_tc<1, 0><<<dim3(U_ / 64, SQ_ / 32, B_), 256>>>(
        attn, value, ctx, SQ_, U_, SK_,
        (long long)SQ_ * SK_, (long long)SK_ * U_, (long long)SQ_ * U_);
}

// round 14
// speedup vs baseline: 1.1163x; 1.0366x over previous
#include <cuda_runtime.h>
#include <cuda_bf16.h>
#include <math_constants.h>

#define B_  8
#define SQ_ 128
#define SK_ 1024
#define U_  256

// Scratch: projections in MIXED layout.
// u%8 in {0,1,2,4,5}: raw value x. u%8 in {3,6,7}: e^{2x} (for exp identity).
__device__ float g_q[B_ * SQ_ * U_];   // 1 MB
__device__ float g_k[B_ * SK_ * U_];   // 8 MB

__device__ __forceinline__ float tanha(float x) {
    float y;
    asm("tanh.approx.f32 %0, %1;" : "=f"(y) : "f"(x));
    return y;
}

// e^{2x} via MUFU ex2: 2^{x * 2*log2(e)}
__device__ __forceinline__ float exp2x(float x) {
    float y;
    float t = x * 2.8853900817779268f;
    asm("ex2.approx.f32 %0, %1;" : "=f"(y) : "f"(t));
    return y;
}

// Division-free reciprocal: magic-constant seed (ALU) + 2 Newton (FMA pipe).
__device__ __forceinline__ float rcp_fma(float den) {
    float y = __uint_as_float(0x7EF311C3u - __float_as_uint(den));
    y = y * (2.0f - den * y);
    y = y * (2.0f - den * y);
    return y;
}

__device__ __forceinline__ unsigned smem_u32(const void* p) {
    return (unsigned)__cvta_generic_to_shared(p);
}

// ---------------------------------------------------------------------------
// bf16 3-term split GEMM helpers
// ---------------------------------------------------------------------------
__device__ __forceinline__ void split_store8(float4 v,
                                             __nv_bfloat16* ph, __nv_bfloat16* pl) {
    __nv_bfloat162 h01 = __floats2bfloat162_rn(v.x, v.y);
    __nv_bfloat162 h23 = __floats2bfloat162_rn(v.z, v.w);
    __nv_bfloat162 l01 = __floats2bfloat162_rn(v.x - __bfloat162float(h01.x),
                                               v.y - __bfloat162float(h01.y));
    __nv_bfloat162 l23 = __floats2bfloat162_rn(v.z - __bfloat162float(h23.x),
                                               v.w - __bfloat162float(h23.y));
    *reinterpret_cast<__nv_bfloat162*>(ph)     = h01;
    *reinterpret_cast<__nv_bfloat162*>(ph + 2) = h23;
    *reinterpret_cast<__nv_bfloat162*>(pl)     = l01;
    *reinterpret_cast<__nv_bfloat162*>(pl + 2) = l23;
}

__device__ __forceinline__ void ldsm_x4(unsigned r[4], unsigned addr) {
    asm volatile("ldmatrix.sync.aligned.m8n8.x4.shared.b16 {%0,%1,%2,%3}, [%4];"
        : "=r"(r[0]), "=r"(r[1]), "=r"(r[2]), "=r"(r[3]) : "r"(addr));
}

__device__ __forceinline__ void ldsm_x4_t(unsigned r[4], unsigned addr) {
    asm volatile("ldmatrix.sync.aligned.m8n8.x4.trans.shared.b16 {%0,%1,%2,%3}, [%4];"
        : "=r"(r[0]), "=r"(r[1]), "=r"(r[2]), "=r"(r[3]) : "r"(addr));
}

__device__ __forceinline__ void mma_bf16(float* d, const unsigned a[4],
                                         unsigned b0, unsigned b1) {
    asm volatile("mma.sync.aligned.m16n8k16.row.col.f32.bf16.bf16.f32 "
        "{%0,%1,%2,%3}, {%4,%5,%6,%7}, {%8,%9}, {%0,%1,%2,%3};"
        : "+f"(d[0]), "+f"(d[1]), "+f"(d[2]), "+f"(d[3])
        : "r"(a[0]), "r"(a[1]), "r"(a[2]), "r"(a[3]), "r"(b0), "r"(b1));
}

// ---------------------------------------------------------------------------
// Tensor-core SGEMM, bf16 3-term split. MIXEPI=1: exp-transform cols with
// col%8 in {3,6,7}: tig==1 -> odd elems (d[1],d[3]); tig==3 -> all four.
// ---------------------------------------------------------------------------
template <int IM, int MIXEPI>
__global__ void gemm_tc(const float* __restrict__ A, const float* __restrict__ Bm,
                        float* __restrict__ C, int M, int N, int K,
                        long long sA, long long sB, long long sC) {
    constexpr int TM = 32 * IM;
    A  += (long long)blockIdx.z * sA;
    Bm += (long long)blockIdx.z * sB;
    C  += (long long)blockIdx.z * sC;

    __shared__ alignas(16) __nv_bfloat16 Ah[TM][40], Al[TM][40];
    __shared__ alignas(16) __nv_bfloat16 Bh[32][72], Bl[32][72];

    const int tid  = threadIdx.x;
    const int lane = tid & 31;
    const int warp = tid >> 5;
    const int wm   = warp >> 2;
    const int wn   = warp & 3;
    const int gid  = lane >> 2;
    const int tig  = lane & 3;
    const int m_base = wm * (16 * IM);
    const int n_base = wn * 16;
    const int m0 = blockIdx.y * TM;
    const int n0 = blockIdx.x * 64;

    const int l8   = lane & 7;
    const int t8   = lane >> 3;
    const int rrow = l8 + ((t8 & 1) << 3);
    const int rcol = (t8 >> 1) << 3;

    const unsigned baseAh = smem_u32(&Ah[0][0]);
    const unsigned baseAl = smem_u32(&Al[0][0]);
    const unsigned baseBh = smem_u32(&Bh[0][0]);
    const unsigned baseBl = smem_u32(&Bl[0][0]);

    float acc[IM][2][4];
#pragma unroll
    for (int im = 0; im < IM; im++)
#pragma unroll
        for (int in = 0; in < 2; in++)
#pragma unroll
            for (int c = 0; c < 4; c++) acc[im][in][c] = 0.0f;

    for (int k0 = 0; k0 < K; k0 += 32) {
#pragma unroll
        for (int it = 0; it < IM; it++) {
            int idx = tid + it * 256;
            int r = idx >> 3;
            int c = (idx & 7) << 2;
            float4 v = *(const float4*)&A[(long long)(m0 + r) * K + k0 + c];
            split_store8(v, &Ah[r][c], &Al[r][c]);
        }
#pragma unroll
        for (int it = 0; it < 2; it++) {
            int idx = tid + it * 256;
            int r = idx >> 4;
            int c = (idx & 15) << 2;
            float4 v = *(const float4*)&Bm[(long long)(k0 + r) * N + n0 + c];
            split_store8(v, &Bh[r][c], &Bl[r][c]);
        }
        __syncthreads();

#pragma unroll
        for (int kk = 0; kk < 2; kk++) {
            const int kb = kk << 4;
            unsigned ah[IM][4], al[IM][4], bh[4], bl[4];
#pragma unroll
            for (int im = 0; im < IM; im++) {
                unsigned ra = ((unsigned)((m_base + 16 * im + rrow) * 40 + kb + rcol)) << 1;
                ldsm_x4(ah[im], baseAh + ra);
                ldsm_x4(al[im], baseAl + ra);
            }
            unsigned rb = ((unsigned)((kb + rrow) * 72 + n_base + rcol)) << 1;
            ldsm_x4_t(bh, baseBh + rb);
            ldsm_x4_t(bl, baseBl + rb);

#pragma unroll
            for (int im = 0; im < IM; im++) {
                mma_bf16(acc[im][0], ah[im], bh[0], bh[1]);
                mma_bf16(acc[im][0], ah[im], bl[0], bl[1]);
                mma_bf16(acc[im][0], al[im], bh[0], bh[1]);
                mma_bf16(acc[im][1], ah[im], bh[2], bh[3]);
                mma_bf16(acc[im][1], ah[im], bl[2], bl[3]);
                mma_bf16(acc[im][1], al[im], bh[2], bh[3]);
            }
        }
        __syncthreads();
    }

    // MIXEPI: d[0],d[2] hold cols == 2*tig (mod 8); d[1],d[3] cols == 2*tig+1.
    // exp set {3,6,7}: tig==1 -> d[1],d[3]; tig==3 -> d[0..3].
#pragma unroll
    for (int im = 0; im < IM; im++) {
#pragma unroll
        for (int in = 0; in < 2; in++) {
            int row = m0 + m_base + 16 * im + gid;
            int col = n0 + n_base + 8 * in + 2 * tig;
            float* d = acc[im][in];
            if (MIXEPI) {
                if (tig == 1) {
                    d[1] = exp2x(d[1]);
                    d[3] = exp2x(d[3]);
                } else if (tig == 3) {
                    d[0] = exp2x(d[0]);
                    d[1] = exp2x(d[1]);
                    d[2] = exp2x(d[2]);
                    d[3] = exp2x(d[3]);
                }
            }
            *(float2*)&C[(long long)row * N + col]       = make_float2(d[0], d[1]);
            *(float2*)&C[(long long)(row + 8) * N + col] = make_float2(d[2], d[3]);
        }
    }
}

// ---------------------------------------------------------------------------
// Scores v9 (5:3 MUFU/exp split): u%8 in {0,1,2,4,5} -> MUFU tanh(q+k).
// u%8 in {3,6,7} are stored as E=e^{2x}; use
//   tanh(q+k) = 1 - 2/(Eq*Ek + 1)
// -> per element: fma + Newton-rcp + fma (0 MUFU, den >= 1: no cancellation).
// The "+w" constants sum to cst = sum of exp-set weights, added at init.
// ---------------------------------------------------------------------------
#define TQ 16

__global__ void scores_kernel(const float* __restrict__ wv, float* __restrict__ attn) {
    const int b  = blockIdx.z;
    const int ib = blockIdx.y;
    const int tid = threadIdx.x;
    const int j  = blockIdx.x * 256 + tid;

    __shared__ float qs[TQ][U_];   // 16 KB (mixed layout)
    __shared__ float wvs[U_];

    const float* qbase = g_q + ((long long)(b * SQ_ + ib * TQ)) * U_;
#pragma unroll
    for (int l = 0; l < 4; l++) {
        int idx = tid + l * 256;
        int row = idx >> 6;
        int col = (idx & 63) << 2;
        *(float4*)&qs[row][col] = *(const float4*)&qbase[(long long)row * U_ + col];
    }
    if (tid < 64) *(float4*)&wvs[tid << 2] = *(const float4*)&wv[tid << 2];
    __syncthreads();

    // Constant part of the exp identity: sum of w over exp-set components.
    float cst = 0.0f;
#pragma unroll
    for (int c = 0; c < U_; c += 8)
        cst += wvs[c + 3] + wvs[c + 6] + wvs[c + 7];

    const float* kp = g_k + ((long long)(b * SK_) + j) * U_;

    float acc[TQ];
#pragma unroll
    for (int i = 0; i < TQ; i++) acc[i] = cst;

    float4 ka = *(const float4*)&kp[0];
    float4 kb = *(const float4*)&kp[4];

    for (int uc = 0; uc < U_; uc += 8) {
        int un = (uc + 8 < U_) ? uc + 8 : uc;   // clamped tail prefetch
        float4 kna = *(const float4*)&kp[un];
        float4 knb = *(const float4*)&kp[un + 4];
        float4 w0 = *(const float4*)&wvs[uc];
        float4 w1 = *(const float4*)&wvs[uc + 4];
        // prescaled exp-path weights (amortized over the i loop)
        float w2a = -2.0f * w0.w;
        float w2b = -2.0f * w1.z;
        float w2c = -2.0f * w1.w;
#pragma unroll
        for (int i = 0; i < TQ; i++) {
            float4 q0 = *(const float4*)&qs[i][uc];        // broadcast LDS
            float4 q1 = *(const float4*)&qs[i][uc + 4];
            float a = acc[i];
            // MUFU path (raw components: u%8 in {0,1,2,4,5})
            a = fmaf(tanha(q0.x + ka.x), w0.x, a);
            a = fmaf(tanha(q0.y + ka.y), w0.y, a);
            a = fmaf(tanha(q0.z + ka.z), w0.z, a);
            a = fmaf(tanha(q1.x + kb.x), w1.x, a);
            a = fmaf(tanha(q1.y + kb.y), w1.y, a);
            // exp path (E-components: u%8 in {3,6,7}); den = Eq*Ek + 1 >= 1
            a = fmaf(w2a, rcp_fma(fmaf(q0.w, ka.w, 1.0f)), a);
            a = fmaf(w2b, rcp_fma(fmaf(q1.z, kb.z, 1.0f)), a);
            a = fmaf(w2c, rcp_fma(fmaf(q1.w, kb.w, 1.0f)), a);
            acc[i] = a;
        }
        ka = kna;
        kb = knb;
    }

    long long base = ((long long)(b * SQ_ + ib * TQ)) * SK_ + j;
#pragma unroll
    for (int i = 0; i < TQ; i++) attn[base + (long long)i * SK_] = acc[i];
}

// ---------------------------------------------------------------------------
// Row softmax over SK=1024, in place. One CTA (256 threads) per (b,i) row.
// ---------------------------------------------------------------------------
__global__ void softmax_kernel(float* __restrict__ attn) {
    float* p = attn + (long long)blockIdx.x * SK_;
    const int tid = threadIdx.x;
    __shared__ float red[8];

    float4 x = *(const float4*)&p[tid << 2];
    float m = fmaxf(fmaxf(x.x, x.y), fmaxf(x.z, x.w));
#pragma unroll
    for (int o = 16; o; o >>= 1) m = fmaxf(m, __shfl_xor_sync(0xffffffffu, m, o));
    if ((tid & 31) == 0) red[tid >> 5] = m;
    __syncthreads();
    float M = red[0];
#pragma unroll
    for (int w = 1; w < 8; w++) M = fmaxf(M, red[w]);

    float4 e;
    e.x = __expf(x.x - M);
    e.y = __expf(x.y - M);
    e.z = __expf(x.z - M);
    e.w = __expf(x.w - M);
    float s = (e.x + e.y) + (e.z + e.w);
#pragma unroll
    for (int o = 16; o; o >>= 1) s += __shfl_xor_sync(0xffffffffu, s, o);
    __syncthreads();
    if ((tid & 31) == 0) red[tid >> 5] = s;
    __syncthreads();
    float S = 0.f;
#pragma unroll
    for (int w = 0; w < 8; w++) S += red[w];
    float inv = 1.0f / S;
    e.x *= inv; e.y *= inv; e.z *= inv; e.w *= inv;
    *(float4*)&p[tid << 2] = e;
}

// ---------------------------------------------------------------------------
extern "C" void kernel_launch(void* const* d_in, const int* in_sizes, int n_in,
                              void* d_out, int out_size) {
    const float* query = (const float*)d_in[0];
    const float* key   = (const float*)d_in[1];
    const float* value = (const float*)d_in[2];
    const float* Wq    = (const float*)d_in[3];
    const float* Wk    = (const float*)d_in[4];
    const float* wv    = (const float*)d_in[5];

    float* out  = (float*)d_out;
    float* ctx  = out;                            // [B, SQ, U]
    float* attn = out + (long long)B_ * SQ_ * U_; // [B, SQ, SK]

    void* pq = nullptr; void* pk = nullptr;
    cudaGetSymbolAddress(&pq, g_q);
    cudaGetSymbolAddress(&pk, g_k);
    float* dq = (float*)pq;
    float* dk = (float*)pk;

    // 1) Projections on tensor cores, MIXED epilogue (exp on u%8 in {3,6,7})
    gemm_tc<2, 1><<<dim3(U_ / 64, (B_ * SQ_) / 64, 1), 256>>>(
        query, Wq, dq, B_ * SQ_, U_, U_, 0, 0, 0);
    gemm_tc<2, 1><<<dim3(U_ / 64, (B_ * SK_) / 64, 1), 256>>>(
        key, Wk, dk, B_ * SK_, U_, U_, 0, 0, 0);

    // 2) Raw scores (5:3 MUFU/exp split) into attn region
    scores_kernel<<<dim3(SK_ / 256, SQ_ / TQ, B_), 256>>>(wv, attn);

    // 3) Softmax in place
    softmax_kernel<<<B_ * SQ_, 256>>>(attn);

    // 4) context = attn @ value (batched, plain epilogue)
    gemm_tc<1, 0><<<dim3(U_ / 64, SQ_ / 32, B_), 256>>>(
        attn, value, ctx, SQ_, U_, SK_,
        (long long)SQ_ * SK_, (long long)SK_ * U_, (long long)SQ_ * U_);
}